// round 8
// baseline (speedup 1.0000x reference)
#include <cuda_runtime.h>
#include <cstdint>
#include <math.h>

#define NB 128
#define NTOK 577
#define NP 576
#define DD 768
#define NG 17
#define NGC 18          // 17 groups + cls row
#define NOCC 10

typedef unsigned long long ull;

// ---- packed f32x2 helpers (sm_103a) ----
__device__ __forceinline__ ull pk2(float a, float b) {
    ull r; asm("mov.b64 %0, {%1,%2};" : "=l"(r) : "f"(a), "f"(b)); return r;
}
__device__ __forceinline__ void fma2(ull &acc, ull a, ull b) {
    asm("fma.rn.f32x2 %0, %1, %2, %0;" : "+l"(acc) : "l"(a), "l"(b));
}
__device__ __forceinline__ float hadd2(ull a) {
    return __uint_as_float((unsigned)a) + __uint_as_float((unsigned)(a >> 32));
}
__device__ __forceinline__ void cpasync16(uint32_t dst, const void* src) {
    asm volatile("cp.async.cg.shared.global [%0], [%1], 16;"
                 :: "r"(dst), "l"(src) : "memory");
}

// scratch (device global; no allocation). Holds MASKED attn after K1.
__device__ float g_scores[(size_t)NB * NG * NP];

// ================= K1: scores + sim + topk + softmax + attn ===============
// (unchanged from R7 — proven at ~70 µs incl. epilogue)
#define K1_THREADS 576
#define TILE_D 32
#define NT (DD / TILE_D)            // 24
#define PITCH 36                    // floats/row: conflict-free LDS.128
#define TILE_FLOATS (32 * PITCH)    // 1152
#define WPITCH 772                  // W row pitch: 9*772*4 % 128 = 16 (bank-split)
#define OFF_W  (18 * 2 * TILE_FLOATS)          // 41472
#define OFF_CD (OFF_W + NGC * WPITCH)          // 55368
#define K1_SMEM_FLOATS (OFF_CD + NP)           // 55944 floats = 223776 B

extern __shared__ float sm1[];

__global__ void __launch_bounds__(K1_THREADS, 1)
k1_scores(const float* __restrict__ x, const float* __restrict__ gw,
          float* __restrict__ out) {
    const int b   = blockIdx.x;
    const int tid = threadIdx.x;
    const int w   = tid >> 5, ln = tid & 31;
    const int li  = ln & 15,  h  = ln >> 4;
    float* s_w  = sm1 + OFF_W;
    float* s_cd = sm1 + OFF_CD;

    const size_t xb = (size_t)b * NTOK * DD;

    for (int i = tid; i < DD * NG; i += K1_THREADS) {
        int d = i / NG, g = i % NG;
        s_w[g * WPITCH + d] = gw[i];
    }
    for (int i = tid; i < DD; i += K1_THREADS) s_w[NG * WPITCH + i] = x[xb + i];

    const uint32_t smem_base = (uint32_t)__cvta_generic_to_shared(sm1);
    const uint32_t buf0 = smem_base + (uint32_t)(w * 2) * TILE_FLOATS * 4;
    const uint32_t buf1 = buf0 + TILE_FLOATS * 4;
    const float* xrow = x + xb + DD + (size_t)(w * 32) * DD;

#pragma unroll
    for (int t = 0; t < 2; ++t) {
        uint32_t dst = t ? buf1 : buf0;
        const float* src = xrow + t * TILE_D;
#pragma unroll
        for (int k = 0; k < 8; ++k) {
            int idx = ln + 32 * k;
            int row = idx >> 3, ch = idx & 7;
            cpasync16(dst + (uint32_t)(row * PITCH + ch * 4) * 4,
                      src + (size_t)row * DD + ch * 4);
        }
        asm volatile("cp.async.commit_group;" ::: "memory");
    }
    __syncthreads();

    ull a0[9], a1[9], nr0 = 0, nr1 = 0;
#pragma unroll
    for (int g = 0; g < 9; ++g) { a0[g] = 0; a1[g] = 0; }

    const float* wbase = s_w + h * 9 * WPITCH;

    for (int t = 0; t < NT; ++t) {
        asm volatile("cp.async.wait_group 1;" ::: "memory");
        __syncwarp();
        const float* xt  = sm1 + (size_t)(w * 2 + (t & 1)) * TILE_FLOATS;
        const float* wd0 = wbase + t * TILE_D;
#pragma unroll
        for (int blk = 0; blk < 8; ++blk) {
            ulonglong2 xv0 = *reinterpret_cast<const ulonglong2*>(
                xt + li * PITCH + blk * 4);
            ulonglong2 xv1 = *reinterpret_cast<const ulonglong2*>(
                xt + (li + 16) * PITCH + blk * 4);
            const float* wdb = wd0 + blk * 4;
#pragma unroll
            for (int gi = 0; gi < 9; ++gi) {
                ulonglong2 wv = *reinterpret_cast<const ulonglong2*>(wdb + gi * WPITCH);
                fma2(a0[gi], xv0.x, wv.x); fma2(a0[gi], xv0.y, wv.y);
                fma2(a1[gi], xv1.x, wv.x); fma2(a1[gi], xv1.y, wv.y);
            }
            fma2(nr0, xv0.x, xv0.x); fma2(nr0, xv0.y, xv0.y);
            fma2(nr1, xv1.x, xv1.x); fma2(nr1, xv1.y, xv1.y);
        }
        __syncwarp();
        if (t + 2 < NT) {
            uint32_t dst = (t & 1) ? buf1 : buf0;
            const float* src = xrow + (t + 2) * TILE_D;
#pragma unroll
            for (int k = 0; k < 8; ++k) {
                int idx = ln + 32 * k;
                int row = idx >> 3, ch = idx & 7;
                cpasync16(dst + (uint32_t)(row * PITCH + ch * 4) * 4,
                          src + (size_t)row * DD + ch * 4);
            }
        }
        asm volatile("cp.async.commit_group;" ::: "memory");
    }

    // epilogue: scores -> smem (tile region dead)
    __syncthreads();
    float* s_sc   = sm1;
    float* s_sim  = sm1 + NG * NP;
    float* s_mask = s_sim + NP;

    const int p0 = w * 32 + li, p1 = p0 + 16;
#pragma unroll
    for (int gi = 0; gi < 9; ++gi) {
        int g = h * 9 + gi;
        float v0 = hadd2(a0[gi]), v1 = hadd2(a1[gi]);
        if (g < NG) {
            s_sc[g * NP + p0] = v0;
            s_sc[g * NP + p1] = v1;
        } else {
            s_cd[p0] = v0;
            s_cd[p1] = v1;
        }
    }
    __syncthreads();
    if (h == 0) {
        // cls-norm factor dropped: positive per-batch constant, ordering-invariant
        s_sim[p0] = s_cd[p0] / fmaxf(sqrtf(hadd2(nr0)), 1e-12f);
        s_sim[p1] = s_cd[p1] / fmaxf(sqrtf(hadd2(nr1)), 1e-12f);
        s_mask[p0] = 1.0f; s_mask[p1] = 1.0f;
    }
    __syncthreads();

    if (tid < 32) {
        for (int k = 0; k < NOCC; ++k) {
            float best = 3.4e38f; int bi = NP;
#pragma unroll
            for (int q = 0; q < NP / 32; ++q) {
                int idx = tid + q * 32;
                float v = s_sim[idx];
                if (v < best || (v == best && idx < bi)) { best = v; bi = idx; }
            }
#pragma unroll
            for (int off = 16; off; off >>= 1) {
                float ov = __shfl_down_sync(0xffffffffu, best, off);
                int   oi = __shfl_down_sync(0xffffffffu, bi, off);
                if (ov < best || (ov == best && oi < bi)) { best = ov; bi = oi; }
            }
            bi = __shfl_sync(0xffffffffu, bi, 0);
            if (tid == 0) { s_sim[bi] = 3.4e38f; s_mask[bi] = 0.0f; }
            __syncwarp();
        }
    }
    __syncthreads();

    {
        const int p = tid;
        const float mk = s_mask[p];
        float tv[NG];
        float m = -3.4e38f;
#pragma unroll
        for (int g = 0; g < NG; ++g) {
            tv[g] = s_sc[g * NP + p] * 10.0f;
            m = fmaxf(m, tv[g]);
        }
        float ssum = 0.f;
#pragma unroll
        for (int g = 0; g < NG; ++g) { tv[g] = __expf(tv[g] - m); ssum += tv[g]; }
        const float inv = 1.0f / ssum;
        float* oat = out + (size_t)NB * NGC * DD + (size_t)b * NG * NP;
#pragma unroll
        for (int g = 0; g < NG; ++g) {
            float a = tv[g] * inv;
            oat[g * NP + p] = (mk != 0.f) ? a : (1.0f / 17.0f);
            g_scores[((size_t)b * NG + g) * NP + p] = (mk != 0.f) ? a : 0.f;
        }
    }
}

// ======================= K3: group features + cls =========================
// grid (NB, 3), block 256. Thread owns column d = by*256+tid.
// 4-stage (16-patch) register prefetch pipeline; pointer-increment addressing.
extern __shared__ float sm3[];

__global__ void __launch_bounds__(256, 2)
k3_features(const float* __restrict__ x, float* __restrict__ out) {
    const int b   = blockIdx.x;
    const int tid = threadIdx.x;
    const int d   = blockIdx.y * 256 + tid;
    float* s_at = sm3;

    for (int i = tid; i < NG * NP; i += 256)
        s_at[i] = g_scores[(size_t)b * NG * NP + i];
    __syncthreads();

    const size_t xb = (size_t)b * NTOK * DD;
    const float* xp = x + xb + DD + d;   // patch 0, column d
    ull acc[NG];
#pragma unroll
    for (int g = 0; g < NG; ++g) acc[g] = 0ull;

    // 4 buffers x 4 patches in registers (MLP = 16)
    float buf[4][4];
#pragma unroll
    for (int u = 0; u < 4; ++u)
#pragma unroll
        for (int i = 0; i < 4; ++i)
            buf[u][i] = xp[(size_t)(4 * u + i) * DD];

    const float* pf = xp + (size_t)16 * DD;   // next patch row to load
    const float* ap = s_at;                   // attn base for current stage

#pragma unroll 1
    for (int sb = 0; sb < NP / 4; sb += 4) {
#pragma unroll
        for (int u = 0; u < 4; ++u) {
            const float c0 = buf[u][0], c1 = buf[u][1];
            const float c2 = buf[u][2], c3 = buf[u][3];
            // prefetch 4 stages ahead (immediates off rolling pf)
            if (sb + u + 4 < NP / 4) {
#pragma unroll
                for (int i = 0; i < 4; ++i)
                    buf[u][i] = pf[(size_t)(4 * u + i) * DD];
            }
            ull x01 = pk2(c0, c1), x23 = pk2(c2, c3);
            const float* au = ap + 4 * u;
#pragma unroll
            for (int g = 0; g < NG; ++g) {
                ulonglong2 at = *reinterpret_cast<const ulonglong2*>(au + g * NP);
                fma2(acc[g], x01, at.x);
                fma2(acc[g], x23, at.y);
            }
        }
        pf += (size_t)16 * DD;
        ap += 16;
    }

    float* ob = out + (size_t)b * NGC * DD;
    ob[d] = x[xb + d];                        // feats[b][0][d] = cls
#pragma unroll
    for (int g = 0; g < NG; ++g)
        ob[(size_t)(1 + g) * DD + d] = hadd2(acc[g]);
}

extern "C" void kernel_launch(void* const* d_in, const int* in_sizes, int n_in,
                              void* d_out, int out_size) {
    const float* x  = (const float*)d_in[0];
    const float* gw = (const float*)d_in[1];
    float* out = (float*)d_out;

    static bool inited = false;
    if (!inited) {
        cudaFuncSetAttribute(k1_scores, cudaFuncAttributeMaxDynamicSharedMemorySize,
                             K1_SMEM_FLOATS * 4);
        cudaFuncSetAttribute(k3_features, cudaFuncAttributeMaxDynamicSharedMemorySize,
                             NG * NP * 4);
        inited = true;
    }

    k1_scores<<<NB, K1_THREADS, K1_SMEM_FLOATS * 4>>>(x, gw, out);
    k3_features<<<dim3(NB, 3), 256, NG * NP * 4>>>(x, out);
}

// round 9
// speedup vs baseline: 1.0123x; 1.0123x over previous
#include <cuda_runtime.h>
#include <cstdint>
#include <math.h>

#define NB 128
#define NTOK 577
#define NP 576
#define DD 768
#define NG 17
#define NGC 18          // 17 groups + cls row
#define NOCC 10

typedef unsigned long long ull;

// ---- packed f32x2 helpers (sm_103a) ----
__device__ __forceinline__ ull pk2(float a, float b) {
    ull r; asm("mov.b64 %0, {%1,%2};" : "=l"(r) : "f"(a), "f"(b)); return r;
}
__device__ __forceinline__ void fma2(ull &acc, ull a, ull b) {
    asm("fma.rn.f32x2 %0, %1, %2, %0;" : "+l"(acc) : "l"(a), "l"(b));
}
__device__ __forceinline__ float hadd2(ull a) {
    return __uint_as_float((unsigned)a) + __uint_as_float((unsigned)(a >> 32));
}
__device__ __forceinline__ void cpasync16(uint32_t dst, const void* src) {
    asm volatile("cp.async.cg.shared.global [%0], [%1], 16;"
                 :: "r"(dst), "l"(src) : "memory");
}

// scratch (device global; no allocation). Holds MASKED attn after K1.
__device__ float g_scores[(size_t)NB * NG * NP];

// ================= K1: scores + sim + topk + softmax + attn ===============
// (unchanged from R7 — proven)
#define K1_THREADS 576
#define TILE_D 32
#define NT (DD / TILE_D)            // 24
#define PITCH 36                    // floats/row: conflict-free LDS.128
#define TILE_FLOATS (32 * PITCH)    // 1152
#define WPITCH 772                  // W row pitch: 9*772*4 % 128 = 16 (bank-split)
#define OFF_W  (18 * 2 * TILE_FLOATS)          // 41472
#define OFF_CD (OFF_W + NGC * WPITCH)          // 55368
#define K1_SMEM_FLOATS (OFF_CD + NP)           // 55944 floats = 223776 B

extern __shared__ float sm1[];

__global__ void __launch_bounds__(K1_THREADS, 1)
k1_scores(const float* __restrict__ x, const float* __restrict__ gw,
          float* __restrict__ out) {
    const int b   = blockIdx.x;
    const int tid = threadIdx.x;
    const int w   = tid >> 5, ln = tid & 31;
    const int li  = ln & 15,  h  = ln >> 4;
    float* s_w  = sm1 + OFF_W;
    float* s_cd = sm1 + OFF_CD;

    const size_t xb = (size_t)b * NTOK * DD;

    for (int i = tid; i < DD * NG; i += K1_THREADS) {
        int d = i / NG, g = i % NG;
        s_w[g * WPITCH + d] = gw[i];
    }
    for (int i = tid; i < DD; i += K1_THREADS) s_w[NG * WPITCH + i] = x[xb + i];

    const uint32_t smem_base = (uint32_t)__cvta_generic_to_shared(sm1);
    const uint32_t buf0 = smem_base + (uint32_t)(w * 2) * TILE_FLOATS * 4;
    const uint32_t buf1 = buf0 + TILE_FLOATS * 4;
    const float* xrow = x + xb + DD + (size_t)(w * 32) * DD;

#pragma unroll
    for (int t = 0; t < 2; ++t) {
        uint32_t dst = t ? buf1 : buf0;
        const float* src = xrow + t * TILE_D;
#pragma unroll
        for (int k = 0; k < 8; ++k) {
            int idx = ln + 32 * k;
            int row = idx >> 3, ch = idx & 7;
            cpasync16(dst + (uint32_t)(row * PITCH + ch * 4) * 4,
                      src + (size_t)row * DD + ch * 4);
        }
        asm volatile("cp.async.commit_group;" ::: "memory");
    }
    __syncthreads();

    ull a0[9], a1[9], nr0 = 0, nr1 = 0;
#pragma unroll
    for (int g = 0; g < 9; ++g) { a0[g] = 0; a1[g] = 0; }

    const float* wbase = s_w + h * 9 * WPITCH;

    for (int t = 0; t < NT; ++t) {
        asm volatile("cp.async.wait_group 1;" ::: "memory");
        __syncwarp();
        const float* xt  = sm1 + (size_t)(w * 2 + (t & 1)) * TILE_FLOATS;
        const float* wd0 = wbase + t * TILE_D;
#pragma unroll
        for (int blk = 0; blk < 8; ++blk) {
            ulonglong2 xv0 = *reinterpret_cast<const ulonglong2*>(
                xt + li * PITCH + blk * 4);
            ulonglong2 xv1 = *reinterpret_cast<const ulonglong2*>(
                xt + (li + 16) * PITCH + blk * 4);
            const float* wdb = wd0 + blk * 4;
#pragma unroll
            for (int gi = 0; gi < 9; ++gi) {
                ulonglong2 wv = *reinterpret_cast<const ulonglong2*>(wdb + gi * WPITCH);
                fma2(a0[gi], xv0.x, wv.x); fma2(a0[gi], xv0.y, wv.y);
                fma2(a1[gi], xv1.x, wv.x); fma2(a1[gi], xv1.y, wv.y);
            }
            fma2(nr0, xv0.x, xv0.x); fma2(nr0, xv0.y, xv0.y);
            fma2(nr1, xv1.x, xv1.x); fma2(nr1, xv1.y, xv1.y);
        }
        __syncwarp();
        if (t + 2 < NT) {
            uint32_t dst = (t & 1) ? buf1 : buf0;
            const float* src = xrow + (t + 2) * TILE_D;
#pragma unroll
            for (int k = 0; k < 8; ++k) {
                int idx = ln + 32 * k;
                int row = idx >> 3, ch = idx & 7;
                cpasync16(dst + (uint32_t)(row * PITCH + ch * 4) * 4,
                          src + (size_t)row * DD + ch * 4);
            }
        }
        asm volatile("cp.async.commit_group;" ::: "memory");
    }

    // epilogue: scores -> smem (tile region dead)
    __syncthreads();
    float* s_sc   = sm1;
    float* s_sim  = sm1 + NG * NP;
    float* s_mask = s_sim + NP;

    const int p0 = w * 32 + li, p1 = p0 + 16;
#pragma unroll
    for (int gi = 0; gi < 9; ++gi) {
        int g = h * 9 + gi;
        float v0 = hadd2(a0[gi]), v1 = hadd2(a1[gi]);
        if (g < NG) {
            s_sc[g * NP + p0] = v0;
            s_sc[g * NP + p1] = v1;
        } else {
            s_cd[p0] = v0;
            s_cd[p1] = v1;
        }
    }
    __syncthreads();
    if (h == 0) {
        // cls-norm factor dropped: positive per-batch constant, ordering-invariant
        s_sim[p0] = s_cd[p0] / fmaxf(sqrtf(hadd2(nr0)), 1e-12f);
        s_sim[p1] = s_cd[p1] / fmaxf(sqrtf(hadd2(nr1)), 1e-12f);
        s_mask[p0] = 1.0f; s_mask[p1] = 1.0f;
    }
    __syncthreads();

    if (tid < 32) {
        for (int k = 0; k < NOCC; ++k) {
            float best = 3.4e38f; int bi = NP;
#pragma unroll
            for (int q = 0; q < NP / 32; ++q) {
                int idx = tid + q * 32;
                float v = s_sim[idx];
                if (v < best || (v == best && idx < bi)) { best = v; bi = idx; }
            }
#pragma unroll
            for (int off = 16; off; off >>= 1) {
                float ov = __shfl_down_sync(0xffffffffu, best, off);
                int   oi = __shfl_down_sync(0xffffffffu, bi, off);
                if (ov < best || (ov == best && oi < bi)) { best = ov; bi = oi; }
            }
            bi = __shfl_sync(0xffffffffu, bi, 0);
            if (tid == 0) { s_sim[bi] = 3.4e38f; s_mask[bi] = 0.0f; }
            __syncwarp();
        }
    }
    __syncthreads();

    {
        const int p = tid;
        const float mk = s_mask[p];
        float tv[NG];
        float m = -3.4e38f;
#pragma unroll
        for (int g = 0; g < NG; ++g) {
            tv[g] = s_sc[g * NP + p] * 10.0f;
            m = fmaxf(m, tv[g]);
        }
        float ssum = 0.f;
#pragma unroll
        for (int g = 0; g < NG; ++g) { tv[g] = __expf(tv[g] - m); ssum += tv[g]; }
        const float inv = 1.0f / ssum;
        float* oat = out + (size_t)NB * NGC * DD + (size_t)b * NG * NP;
#pragma unroll
        for (int g = 0; g < NG; ++g) {
            float a = tv[g] * inv;
            oat[g * NP + p] = (mk != 0.f) ? a : (1.0f / 17.0f);
            g_scores[((size_t)b * NG + g) * NP + p] = (mk != 0.f) ? a : 0.f;
        }
    }
}

// ======================= K3: group features + cls =========================
// grid (NB, 3), block 256, 3 CTAs/SM. Thread owns column d = by*256+tid.
// x tiles [16 patches x 256 cols] cp.async-staged, double-buffered.
#define K3_TP 16
#define K3_NT (NP / K3_TP)            // 36
#define XT_FLOATS (K3_TP * 256)       // 4096 (16 KB)
#define K3_OFF_X (NG * NP)            // 9792
#define K3_SMEM_FLOATS (K3_OFF_X + 2 * XT_FLOATS)   // 17984 floats = 71936 B

extern __shared__ float sm3[];

__global__ void __launch_bounds__(256, 3)
k3_features(const float* __restrict__ x, float* __restrict__ out) {
    const int b   = blockIdx.x;
    const int tid = threadIdx.x;
    const int d   = blockIdx.y * 256 + tid;
    float* s_at = sm3;
    float* xs0  = sm3 + K3_OFF_X;

    const size_t xb = (size_t)b * NTOK * DD;
    const float* xsrc = x + xb + DD + blockIdx.y * 256;   // patch 0, col slice

    const uint32_t xs_base = (uint32_t)__cvta_generic_to_shared(xs0);

    // prologue: stage attn + issue tiles 0,1
    for (int i = tid; i < NG * NP; i += 256)
        s_at[i] = g_scores[(size_t)b * NG * NP + i];
#pragma unroll
    for (int t = 0; t < 2; ++t) {
        uint32_t dst = xs_base + (uint32_t)t * XT_FLOATS * 4;
        const float* src = xsrc + (size_t)t * K3_TP * DD;
#pragma unroll
        for (int k = 0; k < 4; ++k) {
            int idx = tid + 256 * k;
            int row = idx >> 6, ch = idx & 63;
            cpasync16(dst + (uint32_t)(row * 256 + ch * 4) * 4,
                      src + (size_t)row * DD + ch * 4);
        }
        asm volatile("cp.async.commit_group;" ::: "memory");
    }

    ull acc[NG];
#pragma unroll
    for (int g = 0; g < NG; ++g) acc[g] = 0ull;

    for (int t = 0; t < K3_NT; ++t) {
        asm volatile("cp.async.wait_group 1;" ::: "memory");
        __syncthreads();                       // tile t visible to all
        const float* xt = xs0 + (t & 1) * XT_FLOATS;
        const float* at0 = s_at + t * K3_TP;
#pragma unroll
        for (int q = 0; q < K3_TP / 4; ++q) {  // 4 sub-blocks of 4 patches
            float c0 = xt[(4 * q + 0) * 256 + tid];
            float c1 = xt[(4 * q + 1) * 256 + tid];
            float c2 = xt[(4 * q + 2) * 256 + tid];
            float c3 = xt[(4 * q + 3) * 256 + tid];
            ull x01 = pk2(c0, c1), x23 = pk2(c2, c3);
            const float* ap = at0 + 4 * q;
#pragma unroll
            for (int g = 0; g < NG; ++g) {
                ulonglong2 at = *reinterpret_cast<const ulonglong2*>(ap + g * NP);
                fma2(acc[g], x01, at.x);
                fma2(acc[g], x23, at.y);
            }
        }
        __syncthreads();                       // all done reading buffer (t&1)
        if (t + 2 < K3_NT) {
            uint32_t dst = xs_base + (uint32_t)(t & 1) * XT_FLOATS * 4;
            const float* src = xsrc + (size_t)(t + 2) * K3_TP * DD;
#pragma unroll
            for (int k = 0; k < 4; ++k) {
                int idx = tid + 256 * k;
                int row = idx >> 6, ch = idx & 63;
                cpasync16(dst + (uint32_t)(row * 256 + ch * 4) * 4,
                          src + (size_t)row * DD + ch * 4);
            }
        }
        asm volatile("cp.async.commit_group;" ::: "memory");
    }

    float* ob = out + (size_t)b * NGC * DD;
    ob[d] = x[xb + d];                        // feats[b][0][d] = cls
#pragma unroll
    for (int g = 0; g < NG; ++g)
        ob[(size_t)(1 + g) * DD + d] = hadd2(acc[g]);
}

extern "C" void kernel_launch(void* const* d_in, const int* in_sizes, int n_in,
                              void* d_out, int out_size) {
    const float* x  = (const float*)d_in[0];
    const float* gw = (const float*)d_in[1];
    float* out = (float*)d_out;

    static bool inited = false;
    if (!inited) {
        cudaFuncSetAttribute(k1_scores, cudaFuncAttributeMaxDynamicSharedMemorySize,
                             K1_SMEM_FLOATS * 4);
        cudaFuncSetAttribute(k3_features, cudaFuncAttributeMaxDynamicSharedMemorySize,
                             K3_SMEM_FLOATS * 4);
        inited = true;
    }

    k1_scores<<<NB, K1_THREADS, K1_SMEM_FLOATS * 4>>>(x, gw, out);
    k3_features<<<dim3(NB, 3), 256, K3_SMEM_FLOATS * 4>>>(x, out);
}

// round 10
// speedup vs baseline: 1.0148x; 1.0024x over previous
#include <cuda_runtime.h>
#include <cstdint>
#include <math.h>

#define NB 128
#define NTOK 577
#define NP 576
#define DD 768
#define NG 17
#define NGC 18          // 17 groups + cls row
#define NOCC 10

typedef unsigned long long ull;

// ---- packed f32x2 helpers (sm_103a) ----
__device__ __forceinline__ ull pk2(float a, float b) {
    ull r; asm("mov.b64 %0, {%1,%2};" : "=l"(r) : "f"(a), "f"(b)); return r;
}
__device__ __forceinline__ void fma2(ull &acc, ull a, ull b) {
    asm("fma.rn.f32x2 %0, %1, %2, %0;" : "+l"(acc) : "l"(a), "l"(b));
}
__device__ __forceinline__ float hadd2(ull a) {
    return __uint_as_float((unsigned)a) + __uint_as_float((unsigned)(a >> 32));
}
__device__ __forceinline__ void cpasync16(uint32_t dst, const void* src) {
    asm volatile("cp.async.cg.shared.global [%0], [%1], 16;"
                 :: "r"(dst), "l"(src) : "memory");
}

// scratch (device global; no allocation). Holds MASKED attn after K1.
__device__ float g_scores[(size_t)NB * NG * NP];

// ================= K1: scores + sim + topk + softmax + attn ===============
// (unchanged from R7 — proven)
#define K1_THREADS 576
#define TILE_D 32
#define NT (DD / TILE_D)            // 24
#define PITCH 36                    // floats/row: conflict-free LDS.128
#define TILE_FLOATS (32 * PITCH)    // 1152
#define WPITCH 772                  // W row pitch: 9*772*4 % 128 = 16 (bank-split)
#define OFF_W  (18 * 2 * TILE_FLOATS)          // 41472
#define OFF_CD (OFF_W + NGC * WPITCH)          // 55368
#define K1_SMEM_FLOATS (OFF_CD + NP)           // 55944 floats = 223776 B

extern __shared__ float sm1[];

__global__ void __launch_bounds__(K1_THREADS, 1)
k1_scores(const float* __restrict__ x, const float* __restrict__ gw,
          float* __restrict__ out) {
    const int b   = blockIdx.x;
    const int tid = threadIdx.x;
    const int w   = tid >> 5, ln = tid & 31;
    const int li  = ln & 15,  h  = ln >> 4;
    float* s_w  = sm1 + OFF_W;
    float* s_cd = sm1 + OFF_CD;

    const size_t xb = (size_t)b * NTOK * DD;

    for (int i = tid; i < DD * NG; i += K1_THREADS) {
        int d = i / NG, g = i % NG;
        s_w[g * WPITCH + d] = gw[i];
    }
    for (int i = tid; i < DD; i += K1_THREADS) s_w[NG * WPITCH + i] = x[xb + i];

    const uint32_t smem_base = (uint32_t)__cvta_generic_to_shared(sm1);
    const uint32_t buf0 = smem_base + (uint32_t)(w * 2) * TILE_FLOATS * 4;
    const uint32_t buf1 = buf0 + TILE_FLOATS * 4;
    const float* xrow = x + xb + DD + (size_t)(w * 32) * DD;

#pragma unroll
    for (int t = 0; t < 2; ++t) {
        uint32_t dst = t ? buf1 : buf0;
        const float* src = xrow + t * TILE_D;
#pragma unroll
        for (int k = 0; k < 8; ++k) {
            int idx = ln + 32 * k;
            int row = idx >> 3, ch = idx & 7;
            cpasync16(dst + (uint32_t)(row * PITCH + ch * 4) * 4,
                      src + (size_t)row * DD + ch * 4);
        }
        asm volatile("cp.async.commit_group;" ::: "memory");
    }
    __syncthreads();

    ull a0[9], a1[9], nr0 = 0, nr1 = 0;
#pragma unroll
    for (int g = 0; g < 9; ++g) { a0[g] = 0; a1[g] = 0; }

    const float* wbase = s_w + h * 9 * WPITCH;

    for (int t = 0; t < NT; ++t) {
        asm volatile("cp.async.wait_group 1;" ::: "memory");
        __syncwarp();
        const float* xt  = sm1 + (size_t)(w * 2 + (t & 1)) * TILE_FLOATS;
        const float* wd0 = wbase + t * TILE_D;
#pragma unroll
        for (int blk = 0; blk < 8; ++blk) {
            ulonglong2 xv0 = *reinterpret_cast<const ulonglong2*>(
                xt + li * PITCH + blk * 4);
            ulonglong2 xv1 = *reinterpret_cast<const ulonglong2*>(
                xt + (li + 16) * PITCH + blk * 4);
            const float* wdb = wd0 + blk * 4;
#pragma unroll
            for (int gi = 0; gi < 9; ++gi) {
                ulonglong2 wv = *reinterpret_cast<const ulonglong2*>(wdb + gi * WPITCH);
                fma2(a0[gi], xv0.x, wv.x); fma2(a0[gi], xv0.y, wv.y);
                fma2(a1[gi], xv1.x, wv.x); fma2(a1[gi], xv1.y, wv.y);
            }
            fma2(nr0, xv0.x, xv0.x); fma2(nr0, xv0.y, xv0.y);
            fma2(nr1, xv1.x, xv1.x); fma2(nr1, xv1.y, xv1.y);
        }
        __syncwarp();
        if (t + 2 < NT) {
            uint32_t dst = (t & 1) ? buf1 : buf0;
            const float* src = xrow + (t + 2) * TILE_D;
#pragma unroll
            for (int k = 0; k < 8; ++k) {
                int idx = ln + 32 * k;
                int row = idx >> 3, ch = idx & 7;
                cpasync16(dst + (uint32_t)(row * PITCH + ch * 4) * 4,
                          src + (size_t)row * DD + ch * 4);
            }
        }
        asm volatile("cp.async.commit_group;" ::: "memory");
    }

    // epilogue: scores -> smem (tile region dead)
    __syncthreads();
    float* s_sc   = sm1;
    float* s_sim  = sm1 + NG * NP;
    float* s_mask = s_sim + NP;

    const int p0 = w * 32 + li, p1 = p0 + 16;
#pragma unroll
    for (int gi = 0; gi < 9; ++gi) {
        int g = h * 9 + gi;
        float v0 = hadd2(a0[gi]), v1 = hadd2(a1[gi]);
        if (g < NG) {
            s_sc[g * NP + p0] = v0;
            s_sc[g * NP + p1] = v1;
        } else {
            s_cd[p0] = v0;
            s_cd[p1] = v1;
        }
    }
    __syncthreads();
    if (h == 0) {
        // cls-norm factor dropped: positive per-batch constant, ordering-invariant
        s_sim[p0] = s_cd[p0] / fmaxf(sqrtf(hadd2(nr0)), 1e-12f);
        s_sim[p1] = s_cd[p1] / fmaxf(sqrtf(hadd2(nr1)), 1e-12f);
        s_mask[p0] = 1.0f; s_mask[p1] = 1.0f;
    }
    __syncthreads();

    if (tid < 32) {
        for (int k = 0; k < NOCC; ++k) {
            float best = 3.4e38f; int bi = NP;
#pragma unroll
            for (int q = 0; q < NP / 32; ++q) {
                int idx = tid + q * 32;
                float v = s_sim[idx];
                if (v < best || (v == best && idx < bi)) { best = v; bi = idx; }
            }
#pragma unroll
            for (int off = 16; off; off >>= 1) {
                float ov = __shfl_down_sync(0xffffffffu, best, off);
                int   oi = __shfl_down_sync(0xffffffffu, bi, off);
                if (ov < best || (ov == best && oi < bi)) { best = ov; bi = oi; }
            }
            bi = __shfl_sync(0xffffffffu, bi, 0);
            if (tid == 0) { s_sim[bi] = 3.4e38f; s_mask[bi] = 0.0f; }
            __syncwarp();
        }
    }
    __syncthreads();

    {
        const int p = tid;
        const float mk = s_mask[p];
        float tv[NG];
        float m = -3.4e38f;
#pragma unroll
        for (int g = 0; g < NG; ++g) {
            tv[g] = s_sc[g * NP + p] * 10.0f;
            m = fmaxf(m, tv[g]);
        }
        float ssum = 0.f;
#pragma unroll
        for (int g = 0; g < NG; ++g) { tv[g] = __expf(tv[g] - m); ssum += tv[g]; }
        const float inv = 1.0f / ssum;
        float* oat = out + (size_t)NB * NGC * DD + (size_t)b * NG * NP;
#pragma unroll
        for (int g = 0; g < NG; ++g) {
            float a = tv[g] * inv;
            oat[g * NP + p] = (mk != 0.f) ? a : (1.0f / 17.0f);
            g_scores[((size_t)b * NG + g) * NP + p] = (mk != 0.f) ? a : 0.f;
        }
    }
}

// ======================= K3: group features + cls =========================
// grid (NB, 3), block 256, 3 CTAs/SM. Warp w owns 32 columns; warp-private
// double-buffered x tiles [16 patches x 32 cols] via cp.async; __syncwarp only.
#define K3_TP 16
#define K3_NT (NP / K3_TP)            // 36
#define WT_FLOATS (K3_TP * 32)        // 512 floats = 2 KB per buffer
#define K3_OFF_X (NG * NP)            // 9792
#define K3_SMEM_FLOATS (K3_OFF_X + 8 * 2 * WT_FLOATS)   // 17984 floats = 71936 B

extern __shared__ float sm3[];

__global__ void __launch_bounds__(256, 3)
k3_features(const float* __restrict__ x, float* __restrict__ out) {
    const int b   = blockIdx.x;
    const int tid = threadIdx.x;
    const int w   = tid >> 5, ln = tid & 31;
    const int d   = blockIdx.y * 256 + tid;
    float* s_at = sm3;
    float* wt0  = sm3 + K3_OFF_X + w * 2 * WT_FLOATS;

    const size_t xb = (size_t)b * NTOK * DD;
    // this warp's column slice, patch 0
    const float* xsrc = x + xb + DD + blockIdx.y * 256 + w * 32;

    const uint32_t wt_base = (uint32_t)__cvta_generic_to_shared(wt0);

    // prologue: issue warp tiles 0,1 (4 cp.async of 16B per lane per tile)
#pragma unroll
    for (int t = 0; t < 2; ++t) {
        uint32_t dst = wt_base + (uint32_t)t * WT_FLOATS * 4;
        const float* src = xsrc + (size_t)t * K3_TP * DD;
#pragma unroll
        for (int k = 0; k < 4; ++k) {
            int idx = ln + 32 * k;
            int row = idx >> 3, ch = idx & 7;
            cpasync16(dst + (uint32_t)(row * 32 + ch * 4) * 4,
                      src + (size_t)row * DD + ch * 4);
        }
        asm volatile("cp.async.commit_group;" ::: "memory");
    }

    // stage attn cooperatively
    for (int i = tid; i < NG * NP; i += 256)
        s_at[i] = g_scores[(size_t)b * NG * NP + i];
    __syncthreads();   // attn visible to all warps

    ull acc[NG];
#pragma unroll
    for (int g = 0; g < NG; ++g) acc[g] = 0ull;

    for (int t = 0; t < K3_NT; ++t) {
        asm volatile("cp.async.wait_group 1;" ::: "memory");
        __syncwarp();
        const float* xt  = wt0 + (t & 1) * WT_FLOATS;
        const float* at0 = s_at + t * K3_TP;
#pragma unroll
        for (int q = 0; q < K3_TP / 4; ++q) {
            float c0 = xt[(4 * q + 0) * 32 + ln];
            float c1 = xt[(4 * q + 1) * 32 + ln];
            float c2 = xt[(4 * q + 2) * 32 + ln];
            float c3 = xt[(4 * q + 3) * 32 + ln];
            ull x01 = pk2(c0, c1), x23 = pk2(c2, c3);
            const float* ap = at0 + 4 * q;
#pragma unroll
            for (int g = 0; g < NG; ++g) {
                ulonglong2 at = *reinterpret_cast<const ulonglong2*>(ap + g * NP);
                fma2(acc[g], x01, at.x);
                fma2(acc[g], x23, at.y);
            }
        }
        __syncwarp();
        if (t + 2 < K3_NT) {
            uint32_t dst = wt_base + (uint32_t)(t & 1) * WT_FLOATS * 4;
            const float* src = xsrc + (size_t)(t + 2) * K3_TP * DD;
#pragma unroll
            for (int k = 0; k < 4; ++k) {
                int idx = ln + 32 * k;
                int row = idx >> 3, ch = idx & 7;
                cpasync16(dst + (uint32_t)(row * 32 + ch * 4) * 4,
                          src + (size_t)row * DD + ch * 4);
            }
        }
        asm volatile("cp.async.commit_group;" ::: "memory");
    }

    float* ob = out + (size_t)b * NGC * DD;
    ob[d] = x[xb + d];                        // feats[b][0][d] = cls
#pragma unroll
    for (int g = 0; g < NG; ++g)
        ob[(size_t)(1 + g) * DD + d] = hadd2(acc[g]);
}

extern "C" void kernel_launch(void* const* d_in, const int* in_sizes, int n_in,
                              void* d_out, int out_size) {
    const float* x  = (const float*)d_in[0];
    const float* gw = (const float*)d_in[1];
    float* out = (float*)d_out;

    static bool inited = false;
    if (!inited) {
        cudaFuncSetAttribute(k1_scores, cudaFuncAttributeMaxDynamicSharedMemorySize,
                             K1_SMEM_FLOATS * 4);
        cudaFuncSetAttribute(k3_features, cudaFuncAttributeMaxDynamicSharedMemorySize,
                             K3_SMEM_FLOATS * 4);
        inited = true;
    }

    k1_scores<<<NB, K1_THREADS, K1_SMEM_FLOATS * 4>>>(x, gw, out);
    k3_features<<<dim3(NB, 3), 256, K3_SMEM_FLOATS * 4>>>(x, out);
}